// round 1
// baseline (speedup 1.0000x reference)
#include <cuda_runtime.h>
#include <math.h>

#define BB 4
#define SS 2048
#define EE 1024
#define HH 16
#define DD 64
#define ND (HH*DD)    // 1024

// Scratch: head-major [B,H,S,D] fp32 buffers (static __device__ per allocation rules)
__device__ float g_Q[BB*HH*SS*DD];
__device__ float g_K[BB*HH*SS*DD];
__device__ float g_V[BB*HH*SS*DD];
__device__ float g_O[BB*HH*SS*DD];

// ---------------------------------------------------------------------------
// QKV projection: out[b,h,s,d] = sum_e X[b,s,e] * W[e, h*64+d] + bias
// GEMM M=8192, N=1024, K=1024. blockIdx.z selects Q/K/V.
// Tile 64x64, BK=16, 256 threads, 4x4 microtile.
// ---------------------------------------------------------------------------
__global__ __launch_bounds__(256) void qkv_proj_kernel(
    const float* __restrict__ X,
    const float* __restrict__ wQ, const float* __restrict__ bQv,
    const float* __restrict__ wK, const float* __restrict__ bKv,
    const float* __restrict__ wV, const float* __restrict__ bVv)
{
    __shared__ float As[16][64];   // [k][m] transposed
    __shared__ float Bs[16][64];   // [k][n]

    const float* W; const float* bias; float* out;
    if (blockIdx.z == 0)      { W = wQ; bias = bQv; out = g_Q; }
    else if (blockIdx.z == 1) { W = wK; bias = bKv; out = g_K; }
    else                      { W = wV; bias = bVv; out = g_V; }

    const int t  = threadIdx.x;
    const int tx = t & 15, ty = t >> 4;
    const int n0 = blockIdx.x * 64;
    const int m0 = blockIdx.y * 64;

    const int ar  = t & 63, akq = t >> 6;   // A load: row in tile, k-quad (0..3)
    const int bk  = t >> 4, bnq = t & 15;   // B load: k row, n-quad

    float c[4][4];
    #pragma unroll
    for (int i = 0; i < 4; ++i)
        #pragma unroll
        for (int j = 0; j < 4; ++j) c[i][j] = 0.0f;

    const float* Aptr = X + (size_t)(m0 + ar) * EE + akq * 4;
    const float* Bptr = W + (size_t)bk * ND + n0 + bnq * 4;

    for (int kt = 0; kt < EE / 16; ++kt) {
        float4 av = *(const float4*)(Aptr + kt * 16);
        float4 bv = *(const float4*)(Bptr + (size_t)kt * 16 * ND);
        As[akq*4+0][ar] = av.x;
        As[akq*4+1][ar] = av.y;
        As[akq*4+2][ar] = av.z;
        As[akq*4+3][ar] = av.w;
        *(float4*)&Bs[bk][bnq*4] = bv;
        __syncthreads();
        #pragma unroll
        for (int kk = 0; kk < 16; ++kk) {
            float4 a4 = *(const float4*)&As[kk][ty*4];
            float4 b4 = *(const float4*)&Bs[kk][tx*4];
            float ax[4] = {a4.x, a4.y, a4.z, a4.w};
            float bx[4] = {b4.x, b4.y, b4.z, b4.w};
            #pragma unroll
            for (int i = 0; i < 4; ++i)
                #pragma unroll
                for (int j = 0; j < 4; ++j)
                    c[i][j] += ax[i] * bx[j];
        }
        __syncthreads();
    }

    // Epilogue: one 64-wide n-tile == exactly one head
    const int h = n0 >> 6;
    float4 bias4 = *(const float4*)(bias + n0 + tx*4);
    #pragma unroll
    for (int i = 0; i < 4; ++i) {
        int m  = m0 + ty*4 + i;
        int b_ = m >> 11;           // /S
        int s_ = m & (SS - 1);
        float4 v;
        v.x = c[i][0] + bias4.x;
        v.y = c[i][1] + bias4.y;
        v.z = c[i][2] + bias4.z;
        v.w = c[i][3] + bias4.w;
        *(float4*)(out + ((size_t)((b_*HH + h)*SS + s_)) * DD + tx*4) = v;
    }
}

// ---------------------------------------------------------------------------
// Flash attention: per (b,h), 64-row q tiles, online softmax over 32 k-tiles.
// smem: Qs[d][r], KPs shared between K[d][c] and P[c][r] (XOR-swizzled), Vs[c][vd].
// Exactly 48KB static smem.
// ---------------------------------------------------------------------------
__global__ __launch_bounds__(256) void attn_kernel(const int* __restrict__ mask)
{
    __shared__ float Qs[64*64];
    __shared__ float KPs[64*64];
    __shared__ float Vs[64*64];

    const int t  = threadIdx.x;
    const int tx = t & 15, ty = t >> 4;
    const int bh = blockIdx.y;
    const int b_ = bh >> 4;
    const int qbase = blockIdx.x * 64;

    const float* Qg = g_Q + (size_t)bh * SS * DD + (size_t)qbase * DD;
    const float* Kg = g_K + (size_t)bh * SS * DD;
    const float* Vg = g_V + (size_t)bh * SS * DD;

    // Load Q tile transposed: Qs[d][r]
    {
        const int r = t & 63, dq0 = t >> 6;
        #pragma unroll
        for (int it = 0; it < 4; ++it) {
            int d0 = (dq0 + it*4) * 4;
            float4 v = *(const float4*)(Qg + r*DD + d0);
            Qs[(d0+0)*64 + r] = v.x;
            Qs[(d0+1)*64 + r] = v.y;
            Qs[(d0+2)*64 + r] = v.z;
            Qs[(d0+3)*64 + r] = v.w;
        }
    }

    float m_i[4], l_i[4], o[4][4];
    #pragma unroll
    for (int i = 0; i < 4; ++i) {
        m_i[i] = -INFINITY; l_i[i] = 0.0f;
        #pragma unroll
        for (int j = 0; j < 4; ++j) o[i][j] = 0.0f;
    }

    const int swz = (tx & 7) << 2;   // P-store swizzle: f(c) = ((c>>2)&7)<<2, c>>2 == tx
    const int* mbase = mask + ((size_t)b_ * SS + qbase + ty*4) * SS + tx*4;

    for (int kt = 0; kt < SS / 64; ++kt) {
        const float* Kt = Kg + (size_t)kt * 64 * DD;
        const float* Vt = Vg + (size_t)kt * 64 * DD;
        __syncthreads();   // previous PV reads done before overwriting tiles
        {
            const int r = t & 63, dq0 = t >> 6;
            #pragma unroll
            for (int it = 0; it < 4; ++it) {
                int d0 = (dq0 + it*4) * 4;
                float4 v = *(const float4*)(Kt + r*DD + d0);
                KPs[(d0+0)*64 + r] = v.x;
                KPs[(d0+1)*64 + r] = v.y;
                KPs[(d0+2)*64 + r] = v.z;
                KPs[(d0+3)*64 + r] = v.w;
            }
            const int vc0 = t >> 4, vq = t & 15;
            #pragma unroll
            for (int it = 0; it < 4; ++it) {
                int cc = vc0 + it*16;
                *(float4*)&Vs[cc*64 + vq*4] = *(const float4*)(Vt + cc*DD + vq*4);
            }
        }
        __syncthreads();

        // S = Q K^T
        float sc[4][4];
        #pragma unroll
        for (int i = 0; i < 4; ++i)
            #pragma unroll
            for (int j = 0; j < 4; ++j) sc[i][j] = 0.0f;
        #pragma unroll 8
        for (int kk = 0; kk < 64; ++kk) {
            float4 a4 = *(const float4*)&Qs[kk*64 + ty*4];
            float4 b4 = *(const float4*)&KPs[kk*64 + tx*4];
            float ax[4] = {a4.x, a4.y, a4.z, a4.w};
            float bx[4] = {b4.x, b4.y, b4.z, b4.w};
            #pragma unroll
            for (int i = 0; i < 4; ++i)
                #pragma unroll
                for (int j = 0; j < 4; ++j)
                    sc[i][j] += ax[i] * bx[j];
        }

        // mask + scale + online softmax update
        const int kb = kt * 64;
        #pragma unroll
        for (int i = 0; i < 4; ++i) {
            int4 mk = *(const int4*)(mbase + (size_t)i * SS + kb);
            sc[i][0] = mk.x ? sc[i][0] * 0.125f : -1e9f;
            sc[i][1] = mk.y ? sc[i][1] * 0.125f : -1e9f;
            sc[i][2] = mk.z ? sc[i][2] * 0.125f : -1e9f;
            sc[i][3] = mk.w ? sc[i][3] * 0.125f : -1e9f;
            float tm = fmaxf(fmaxf(sc[i][0], sc[i][1]), fmaxf(sc[i][2], sc[i][3]));
            tm = fmaxf(tm, __shfl_xor_sync(0xffffffffu, tm, 1));
            tm = fmaxf(tm, __shfl_xor_sync(0xffffffffu, tm, 2));
            tm = fmaxf(tm, __shfl_xor_sync(0xffffffffu, tm, 4));
            tm = fmaxf(tm, __shfl_xor_sync(0xffffffffu, tm, 8));
            float mn = fmaxf(m_i[i], tm);
            float al = __expf(m_i[i] - mn);
            m_i[i] = mn;
            float p0 = __expf(sc[i][0] - mn);
            float p1 = __expf(sc[i][1] - mn);
            float p2 = __expf(sc[i][2] - mn);
            float p3 = __expf(sc[i][3] - mn);
            sc[i][0] = p0; sc[i][1] = p1; sc[i][2] = p2; sc[i][3] = p3;
            float rs = (p0 + p1) + (p2 + p3);
            rs += __shfl_xor_sync(0xffffffffu, rs, 1);
            rs += __shfl_xor_sync(0xffffffffu, rs, 2);
            rs += __shfl_xor_sync(0xffffffffu, rs, 4);
            rs += __shfl_xor_sync(0xffffffffu, rs, 8);
            l_i[i] = l_i[i] * al + rs;
            o[i][0] *= al; o[i][1] *= al; o[i][2] *= al; o[i][3] *= al;
        }

        __syncthreads();   // all K reads done before P overwrites KPs
        // store P[c][r] swizzled
        {
            const int rb = (ty*4) ^ swz;
            #pragma unroll
            for (int j = 0; j < 4; ++j) {
                int cc = tx*4 + j;
                #pragma unroll
                for (int i = 0; i < 4; ++i)
                    KPs[cc*64 + rb + i] = sc[i][j];
            }
        }
        __syncthreads();

        // O += P V
        #pragma unroll 8
        for (int cc = 0; cc < 64; ++cc) {
            float4 a4 = *(const float4*)&KPs[cc*64 + ((ty*4) ^ (((cc >> 2) & 7) << 2))];
            float4 b4 = *(const float4*)&Vs[cc*64 + tx*4];
            float ax[4] = {a4.x, a4.y, a4.z, a4.w};
            float bx[4] = {b4.x, b4.y, b4.z, b4.w};
            #pragma unroll
            for (int i = 0; i < 4; ++i)
                #pragma unroll
                for (int j = 0; j < 4; ++j)
                    o[i][j] += ax[i] * bx[j];
        }
    }

    // normalize + write
    #pragma unroll
    for (int i = 0; i < 4; ++i) {
        float inv = 1.0f / l_i[i];
        float4 v;
        v.x = o[i][0] * inv; v.y = o[i][1] * inv;
        v.z = o[i][2] * inv; v.w = o[i][3] * inv;
        *(float4*)(g_O + (size_t)bh * SS * DD + (size_t)(qbase + ty*4 + i) * DD + tx*4) = v;
    }
}

// ---------------------------------------------------------------------------
// Output projection: out[b,s,:] = concat_h O[b,h,s,:] @ wO + bO
// A gathered from head-major g_O. Same tiling as qkv_proj.
// ---------------------------------------------------------------------------
__global__ __launch_bounds__(256) void out_proj_kernel(
    const float* __restrict__ wO, const float* __restrict__ bO,
    float* __restrict__ out)
{
    __shared__ float As[16][64];
    __shared__ float Bs[16][64];

    const int t  = threadIdx.x;
    const int tx = t & 15, ty = t >> 4;
    const int n0 = blockIdx.x * 64;
    const int m0 = blockIdx.y * 64;

    const int ar  = t & 63, akq = t >> 6;
    const int bk  = t >> 4, bnq = t & 15;

    const int m  = m0 + ar;
    const int b_ = m >> 11;
    const int s_ = m & (SS - 1);
    const float* Abase = g_O + ((size_t)b_ * HH * SS + s_) * DD;

    float c[4][4];
    #pragma unroll
    for (int i = 0; i < 4; ++i)
        #pragma unroll
        for (int j = 0; j < 4; ++j) c[i][j] = 0.0f;

    for (int kt = 0; kt < ND / 16; ++kt) {
        int k = kt*16 + akq*4;
        float4 av = *(const float4*)(Abase + (size_t)(k >> 6) * SS * DD + (k & 63));
        float4 bv = *(const float4*)(wO + (size_t)(kt*16 + bk) * EE + n0 + bnq*4);
        As[akq*4+0][ar] = av.x;
        As[akq*4+1][ar] = av.y;
        As[akq*4+2][ar] = av.z;
        As[akq*4+3][ar] = av.w;
        *(float4*)&Bs[bk][bnq*4] = bv;
        __syncthreads();
        #pragma unroll
        for (int kk = 0; kk < 16; ++kk) {
            float4 a4 = *(const float4*)&As[kk][ty*4];
            float4 b4 = *(const float4*)&Bs[kk][tx*4];
            float ax[4] = {a4.x, a4.y, a4.z, a4.w};
            float bx[4] = {b4.x, b4.y, b4.z, b4.w};
            #pragma unroll
            for (int i = 0; i < 4; ++i)
                #pragma unroll
                for (int j = 0; j < 4; ++j)
                    c[i][j] += ax[i] * bx[j];
        }
        __syncthreads();
    }

    float4 bias4 = *(const float4*)(bO + n0 + tx*4);
    #pragma unroll
    for (int i = 0; i < 4; ++i) {
        float4 v;
        v.x = c[i][0] + bias4.x;
        v.y = c[i][1] + bias4.y;
        v.z = c[i][2] + bias4.z;
        v.w = c[i][3] + bias4.w;
        *(float4*)(out + (size_t)(m0 + ty*4 + i) * EE + n0 + tx*4) = v;
    }
}

extern "C" void kernel_launch(void* const* d_in, const int* in_sizes, int n_in,
                              void* d_out, int out_size)
{
    const float* X    = (const float*)d_in[0];
    const int*   mask = (const int*)  d_in[1];
    const float* wQ   = (const float*)d_in[2];
    const float* bQ   = (const float*)d_in[3];
    const float* wK   = (const float*)d_in[4];
    const float* bK   = (const float*)d_in[5];
    const float* wV   = (const float*)d_in[6];
    const float* bV   = (const float*)d_in[7];
    const float* wO   = (const float*)d_in[8];
    const float* bO   = (const float*)d_in[9];
    float* out = (float*)d_out;

    qkv_proj_kernel<<<dim3(16, 128, 3), 256>>>(X, wQ, bQ, wK, bK, wV, bV);
    attn_kernel<<<dim3(32, 64), 256>>>(mask);
    out_proj_kernel<<<dim3(16, 128), 256>>>(wO, bO, out);
}

// round 2
// speedup vs baseline: 1.2678x; 1.2678x over previous
#include <cuda_runtime.h>
#include <math.h>

#define BB 4
#define SS 2048
#define EE 1024
#define HH 16
#define DD 64
#define ND (HH*DD)    // 1024

__device__ float g_Q[BB*HH*SS*DD];
__device__ float g_K[BB*HH*SS*DD];
__device__ float g_V[BB*HH*SS*DD];
__device__ float g_O[BB*HH*SS*DD];

// ---------------------------------------------------------------------------
// QKV projection GEMM: 128x128 tile, BK=8, 256 threads, 8x8 microtile,
// double-buffered smem + register prefetch.
// out[b,h,s,d] = sum_e X[b,s,e] * W[e, h*64+d] + bias. M=8192,N=1024,K=1024.
// ---------------------------------------------------------------------------
__global__ __launch_bounds__(256) void qkv_proj_kernel(
    const float* __restrict__ X,
    const float* __restrict__ wQ, const float* __restrict__ bQv,
    const float* __restrict__ wK, const float* __restrict__ bKv,
    const float* __restrict__ wV, const float* __restrict__ bVv)
{
    __shared__ float As[2][8][128];
    __shared__ float Bs[2][8][128];

    const float* W; const float* bias; float* out;
    if (blockIdx.z == 0)      { W = wQ; bias = bQv; out = g_Q; }
    else if (blockIdx.z == 1) { W = wK; bias = bKv; out = g_K; }
    else                      { W = wV; bias = bVv; out = g_V; }

    const int t  = threadIdx.x;
    const int tx = t & 15, ty = t >> 4;
    const int n0 = blockIdx.x * 128;
    const int m0 = blockIdx.y * 128;

    const int ar = t >> 1, ac = t & 1;     // A: 128 rows x 2 col-quads
    const int br = t >> 5, bc = t & 31;    // B: 8 rows x 32 col-quads

    const float* Ap = X + (size_t)(m0 + ar) * EE + ac * 4;
    const float* Bp = W + (size_t)br * ND + n0 + bc * 4;

    float acc[8][8];
    #pragma unroll
    for (int i = 0; i < 8; ++i)
        #pragma unroll
        for (int j = 0; j < 8; ++j) acc[i][j] = 0.0f;

    float4 pa = *(const float4*)(Ap);
    float4 pb = *(const float4*)(Bp);
    As[0][ac*4+0][ar] = pa.x;
    As[0][ac*4+1][ar] = pa.y;
    As[0][ac*4+2][ar] = pa.z;
    As[0][ac*4+3][ar] = pa.w;
    *(float4*)&Bs[0][br][bc*4] = pb;
    __syncthreads();

    const int NT = EE / 8;   // 128
    for (int kt = 0; kt < NT; ++kt) {
        const int cur = kt & 1;
        if (kt + 1 < NT) {
            pa = *(const float4*)(Ap + (kt + 1) * 8);
            pb = *(const float4*)(Bp + (size_t)(kt + 1) * 8 * ND);
        }
        #pragma unroll
        for (int kk = 0; kk < 8; ++kk) {
            float4 a0 = *(const float4*)&As[cur][kk][ty*4];
            float4 a1 = *(const float4*)&As[cur][kk][ty*4 + 64];
            float4 b0 = *(const float4*)&Bs[cur][kk][tx*4];
            float4 b1 = *(const float4*)&Bs[cur][kk][tx*4 + 64];
            float av[8] = {a0.x,a0.y,a0.z,a0.w, a1.x,a1.y,a1.z,a1.w};
            float bv[8] = {b0.x,b0.y,b0.z,b0.w, b1.x,b1.y,b1.z,b1.w};
            #pragma unroll
            for (int i = 0; i < 8; ++i)
                #pragma unroll
                for (int j = 0; j < 8; ++j)
                    acc[i][j] += av[i] * bv[j];
        }
        if (kt + 1 < NT) {
            const int nb = cur ^ 1;
            As[nb][ac*4+0][ar] = pa.x;
            As[nb][ac*4+1][ar] = pa.y;
            As[nb][ac*4+2][ar] = pa.z;
            As[nb][ac*4+3][ar] = pa.w;
            *(float4*)&Bs[nb][br][bc*4] = pb;
        }
        __syncthreads();
    }

    // epilogue: cols tx*4 (head h0) and tx*4+64 (head h0+1)
    const int h0 = n0 >> 6;
    float4 bias0 = *(const float4*)(bias + n0 + tx*4);
    float4 bias1 = *(const float4*)(bias + n0 + 64 + tx*4);
    #pragma unroll
    for (int i = 0; i < 8; ++i) {
        int m  = m0 + ty*4 + (i & 3) + ((i >> 2) << 6);
        int b_ = m >> 11;
        int s_ = m & (SS - 1);
        float4 v0, v1;
        v0.x = acc[i][0] + bias0.x; v0.y = acc[i][1] + bias0.y;
        v0.z = acc[i][2] + bias0.z; v0.w = acc[i][3] + bias0.w;
        v1.x = acc[i][4] + bias1.x; v1.y = acc[i][5] + bias1.y;
        v1.z = acc[i][6] + bias1.z; v1.w = acc[i][7] + bias1.w;
        *(float4*)(out + ((size_t)((b_*HH + h0  )*SS + s_)) * DD + tx*4) = v0;
        *(float4*)(out + ((size_t)((b_*HH + h0+1)*SS + s_)) * DD + tx*4) = v1;
    }
}

// ---------------------------------------------------------------------------
// Flash attention: 128 q-rows per block, 64-col k-tiles, 256 threads,
// 8x4 microtile. Dynamic smem 80KB: Qs[d][128] + (K[d][64] | P[c][128]) + V[c][64].
// ---------------------------------------------------------------------------
#define ATTN_SMEM (80 * 1024)

__global__ __launch_bounds__(256) void attn_kernel(const int* __restrict__ mask)
{
    extern __shared__ float sm[];
    float* Qs  = sm;                 // 64 * 128
    float* KPs = sm + 64*128;        // K: 64*64 / P: 64*128
    float* Vs  = sm + 2*64*128;      // 64 * 64

    const int t  = threadIdx.x;
    const int tx = t & 15, ty = t >> 4;
    const int bh = blockIdx.y;
    const int b_ = bh >> 4;
    const int qbase = blockIdx.x * 128;

    const float* Qg = g_Q + (size_t)bh * SS * DD + (size_t)qbase * DD;
    const float* Kg = g_K + (size_t)bh * SS * DD;
    const float* Vg = g_V + (size_t)bh * SS * DD;

    // load Q tile transposed: Qs[d][r], 128 rows x 64 d
    #pragma unroll
    for (int it = 0; it < 8; ++it) {
        int idx = t + it * 256;
        int r = idx & 127, dq = idx >> 7;   // dq 0..15
        float4 v = *(const float4*)(Qg + (size_t)r * DD + dq * 4);
        Qs[(dq*4+0)*128 + r] = v.x;
        Qs[(dq*4+1)*128 + r] = v.y;
        Qs[(dq*4+2)*128 + r] = v.z;
        Qs[(dq*4+3)*128 + r] = v.w;
    }

    float m_i[8], l_i[8], o[8][4];
    #pragma unroll
    for (int i = 0; i < 8; ++i) {
        m_i[i] = -INFINITY; l_i[i] = 0.0f;
        #pragma unroll
        for (int j = 0; j < 4; ++j) o[i][j] = 0.0f;
    }

    const int swz = (tx & 7) << 2;
    const int* mrow[2];
    mrow[0] = mask + ((size_t)b_ * SS + qbase + ty*4) * SS + tx*4;
    mrow[1] = mrow[0] + (size_t)64 * SS;

    for (int kt = 0; kt < SS / 64; ++kt) {
        const float* Kt = Kg + (size_t)kt * 64 * DD;
        const float* Vt = Vg + (size_t)kt * 64 * DD;
        __syncthreads();   // prior PV reads done
        // K transposed: KPs[d][c]
        #pragma unroll
        for (int it = 0; it < 4; ++it) {
            int idx = t + it * 256;
            int r = idx & 63, dq = idx >> 6;   // dq 0..15
            float4 v = *(const float4*)(Kt + (size_t)r * DD + dq * 4);
            KPs[(dq*4+0)*64 + r] = v.x;
            KPs[(dq*4+1)*64 + r] = v.y;
            KPs[(dq*4+2)*64 + r] = v.z;
            KPs[(dq*4+3)*64 + r] = v.w;
        }
        // V direct: Vs[c][vd]
        #pragma unroll
        for (int it = 0; it < 4; ++it) {
            int idx = t + it * 256;
            int c = idx >> 4, q = idx & 15;
            *(float4*)&Vs[c*64 + q*4] = *(const float4*)(Vt + (size_t)c * DD + q*4);
        }
        __syncthreads();

        // S = Q^T-tile . K-tile : rows ty*4+{0..3}, ty*4+64+{0..3}; cols tx*4+{0..3}
        float sc[8][4];
        #pragma unroll
        for (int i = 0; i < 8; ++i)
            #pragma unroll
            for (int j = 0; j < 4; ++j) sc[i][j] = 0.0f;
        #pragma unroll 8
        for (int kk = 0; kk < 64; ++kk) {
            float4 a0 = *(const float4*)&Qs[kk*128 + ty*4];
            float4 a1 = *(const float4*)&Qs[kk*128 + ty*4 + 64];
            float4 b  = *(const float4*)&KPs[kk*64 + tx*4];
            float av[8] = {a0.x,a0.y,a0.z,a0.w, a1.x,a1.y,a1.z,a1.w};
            float bv[4] = {b.x,b.y,b.z,b.w};
            #pragma unroll
            for (int i = 0; i < 8; ++i)
                #pragma unroll
                for (int j = 0; j < 4; ++j)
                    sc[i][j] += av[i] * bv[j];
        }

        // mask + scale + online softmax
        const int kb = kt * 64;
        #pragma unroll
        for (int i = 0; i < 8; ++i) {
            int4 mk = *(const int4*)(mrow[i >> 2] + (size_t)(i & 3) * SS + kb);
            sc[i][0] = mk.x ? sc[i][0] * 0.125f : -1e9f;
            sc[i][1] = mk.y ? sc[i][1] * 0.125f : -1e9f;
            sc[i][2] = mk.z ? sc[i][2] * 0.125f : -1e9f;
            sc[i][3] = mk.w ? sc[i][3] * 0.125f : -1e9f;
            float tm = fmaxf(fmaxf(sc[i][0], sc[i][1]), fmaxf(sc[i][2], sc[i][3]));
            tm = fmaxf(tm, __shfl_xor_sync(0xffffffffu, tm, 1));
            tm = fmaxf(tm, __shfl_xor_sync(0xffffffffu, tm, 2));
            tm = fmaxf(tm, __shfl_xor_sync(0xffffffffu, tm, 4));
            tm = fmaxf(tm, __shfl_xor_sync(0xffffffffu, tm, 8));
            float mn = fmaxf(m_i[i], tm);
            float al = __expf(m_i[i] - mn);
            m_i[i] = mn;
            float p0 = __expf(sc[i][0] - mn);
            float p1 = __expf(sc[i][1] - mn);
            float p2 = __expf(sc[i][2] - mn);
            float p3 = __expf(sc[i][3] - mn);
            sc[i][0] = p0; sc[i][1] = p1; sc[i][2] = p2; sc[i][3] = p3;
            float rs = (p0 + p1) + (p2 + p3);
            rs += __shfl_xor_sync(0xffffffffu, rs, 1);
            rs += __shfl_xor_sync(0xffffffffu, rs, 2);
            rs += __shfl_xor_sync(0xffffffffu, rs, 4);
            rs += __shfl_xor_sync(0xffffffffu, rs, 8);
            l_i[i] = l_i[i] * al + rs;
            o[i][0] *= al; o[i][1] *= al; o[i][2] *= al; o[i][3] *= al;
        }

        __syncthreads();   // K reads done before P overwrite
        // store P[c][r] swizzled, float4 along rows
        {
            const int rb = (ty*4) ^ swz;
            #pragma unroll
            for (int j = 0; j < 4; ++j) {
                int c = tx*4 + j;
                float4 v0 = make_float4(sc[0][j], sc[1][j], sc[2][j], sc[3][j]);
                float4 v1 = make_float4(sc[4][j], sc[5][j], sc[6][j], sc[7][j]);
                *(float4*)&KPs[c*128 + rb]      = v0;
                *(float4*)&KPs[c*128 + rb + 64] = v1;
            }
        }
        __syncthreads();

        // O += P V
        #pragma unroll 8
        for (int cc = 0; cc < 64; ++cc) {
            const int sw2 = ((cc >> 2) & 7) << 2;
            float4 a0 = *(const float4*)&KPs[cc*128 + ((ty*4) ^ sw2)];
            float4 a1 = *(const float4*)&KPs[cc*128 + ((ty*4) ^ sw2) + 64];
            float4 b  = *(const float4*)&Vs[cc*64 + tx*4];
            float av[8] = {a0.x,a0.y,a0.z,a0.w, a1.x,a1.y,a1.z,a1.w};
            float bv[4] = {b.x,b.y,b.z,b.w};
            #pragma unroll
            for (int i = 0; i < 8; ++i)
                #pragma unroll
                for (int j = 0; j < 4; ++j)
                    o[i][j] += av[i] * bv[j];
        }
    }

    // normalize + write
    #pragma unroll
    for (int i = 0; i < 8; ++i) {
        int row = qbase + ty*4 + (i & 3) + ((i >> 2) << 6);
        float inv = 1.0f / l_i[i];
        float4 v;
        v.x = o[i][0]*inv; v.y = o[i][1]*inv; v.z = o[i][2]*inv; v.w = o[i][3]*inv;
        *(float4*)(g_O + (size_t)bh * SS * DD + (size_t)row * DD + tx*4) = v;
    }
}

// ---------------------------------------------------------------------------
// Output projection: same 128x128/BK=8/8x8 scheme; A gathered from head-major g_O.
// ---------------------------------------------------------------------------
__global__ __launch_bounds__(256) void out_proj_kernel(
    const float* __restrict__ wO, const float* __restrict__ bO,
    float* __restrict__ out)
{
    __shared__ float As[2][8][128];
    __shared__ float Bs[2][8][128];

    const int t  = threadIdx.x;
    const int tx = t & 15, ty = t >> 4;
    const int n0 = blockIdx.x * 128;
    const int m0 = blockIdx.y * 128;

    const int ar = t >> 1, ac = t & 1;
    const int br = t >> 5, bc = t & 31;

    const int m  = m0 + ar;
    const int b_ = m >> 11;
    const int s_ = m & (SS - 1);
    const float* Abase = g_O + ((size_t)b_ * HH * SS + s_) * DD;
    const float* Bp = wO + (size_t)br * EE + n0 + bc * 4;

    float acc[8][8];
    #pragma unroll
    for (int i = 0; i < 8; ++i)
        #pragma unroll
        for (int j = 0; j < 8; ++j) acc[i][j] = 0.0f;

    auto loadA = [&](int kt) -> float4 {
        int k = kt*8 + ac*4;
        return *(const float4*)(Abase + (size_t)(k >> 6) * SS * DD + (k & 63));
    };

    float4 pa = loadA(0);
    float4 pb = *(const float4*)(Bp);
    As[0][ac*4+0][ar] = pa.x;
    As[0][ac*4+1][ar] = pa.y;
    As[0][ac*4+2][ar] = pa.z;
    As[0][ac*4+3][ar] = pa.w;
    *(float4*)&Bs[0][br][bc*4] = pb;
    __syncthreads();

    const int NT = ND / 8;   // 128
    for (int kt = 0; kt < NT; ++kt) {
        const int cur = kt & 1;
        if (kt + 1 < NT) {
            pa = loadA(kt + 1);
            pb = *(const float4*)(Bp + (size_t)(kt + 1) * 8 * EE);
        }
        #pragma unroll
        for (int kk = 0; kk < 8; ++kk) {
            float4 a0 = *(const float4*)&As[cur][kk][ty*4];
            float4 a1 = *(const float4*)&As[cur][kk][ty*4 + 64];
            float4 b0 = *(const float4*)&Bs[cur][kk][tx*4];
            float4 b1 = *(const float4*)&Bs[cur][kk][tx*4 + 64];
            float av[8] = {a0.x,a0.y,a0.z,a0.w, a1.x,a1.y,a1.z,a1.w};
            float bv[8] = {b0.x,b0.y,b0.z,b0.w, b1.x,b1.y,b1.z,b1.w};
            #pragma unroll
            for (int i = 0; i < 8; ++i)
                #pragma unroll
                for (int j = 0; j < 8; ++j)
                    acc[i][j] += av[i] * bv[j];
        }
        if (kt + 1 < NT) {
            const int nb = cur ^ 1;
            As[nb][ac*4+0][ar] = pa.x;
            As[nb][ac*4+1][ar] = pa.y;
            As[nb][ac*4+2][ar] = pa.z;
            As[nb][ac*4+3][ar] = pa.w;
            *(float4*)&Bs[nb][br][bc*4] = pb;
        }
        __syncthreads();
    }

    float4 bias0 = *(const float4*)(bO + n0 + tx*4);
    float4 bias1 = *(const float4*)(bO + n0 + 64 + tx*4);
    #pragma unroll
    for (int i = 0; i < 8; ++i) {
        int row = m0 + ty*4 + (i & 3) + ((i >> 2) << 6);
        float4 v0, v1;
        v0.x = acc[i][0] + bias0.x; v0.y = acc[i][1] + bias0.y;
        v0.z = acc[i][2] + bias0.z; v0.w = acc[i][3] + bias0.w;
        v1.x = acc[i][4] + bias1.x; v1.y = acc[i][5] + bias1.y;
        v1.z = acc[i][6] + bias1.z; v1.w = acc[i][7] + bias1.w;
        *(float4*)(out + (size_t)row * EE + n0 + tx*4)      = v0;
        *(float4*)(out + (size_t)row * EE + n0 + 64 + tx*4) = v1;
    }
}

extern "C" void kernel_launch(void* const* d_in, const int* in_sizes, int n_in,
                              void* d_out, int out_size)
{
    const float* X    = (const float*)d_in[0];
    const int*   mask = (const int*)  d_in[1];
    const float* wQ   = (const float*)d_in[2];
    const float* bQ   = (const float*)d_in[3];
    const float* wK   = (const float*)d_in[4];
    const float* bK   = (const float*)d_in[5];
    const float* wV   = (const float*)d_in[6];
    const float* bV   = (const float*)d_in[7];
    const float* wO   = (const float*)d_in[8];
    const float* bO   = (const float*)d_in[9];
    float* out = (float*)d_out;

    cudaFuncSetAttribute(attn_kernel, cudaFuncAttributeMaxDynamicSharedMemorySize, ATTN_SMEM);

    qkv_proj_kernel<<<dim3(8, 64, 3), 256>>>(X, wQ, bQ, wK, bK, wV, bV);
    attn_kernel<<<dim3(16, 64), 256, ATTN_SMEM>>>(mask);
    out_proj_kernel<<<dim3(8, 64), 256>>>(wO, bO, out);
}

// round 4
// speedup vs baseline: 1.7393x; 1.3719x over previous
#include <cuda_runtime.h>
#include <cuda_bf16.h>
#include <math.h>
#include <stdint.h>

#define BB 4
#define SS 2048
#define EE 1024
#define HH 16
#define DD 64
#define ND 1024
#define MM (BB*SS)   // 8192

// fp32 head-major buffers for attention
__device__ float g_Q[BB*HH*SS*DD];
__device__ float g_K[BB*HH*SS*DD];
__device__ float g_V[BB*HH*SS*DD];
__device__ float g_O[BB*HH*SS*DD];

// bf16 split operands: A (X, later gathered O), W (4 matrices, stored [n][k])
__device__ __nv_bfloat16 g_Ahi[MM*EE];
__device__ __nv_bfloat16 g_Alo[MM*EE];
__device__ __nv_bfloat16 g_Whi[4*ND*EE];
__device__ __nv_bfloat16 g_Wlo[4*ND*EE];

// ---------------------------------------------------------------------------
// PTX helpers (compute_103-safe: mma.sync / ldmatrix / cp.async only)
// ---------------------------------------------------------------------------
__device__ __forceinline__ uint32_t smem_u32(const void* p) {
    return (uint32_t)__cvta_generic_to_shared(p);
}
__device__ __forceinline__ void ldsm4(uint32_t* r, uint32_t addr) {
    asm volatile("ldmatrix.sync.aligned.m8n8.x4.shared.b16 {%0,%1,%2,%3}, [%4];"
                 : "=r"(r[0]), "=r"(r[1]), "=r"(r[2]), "=r"(r[3]) : "r"(addr));
}
__device__ __forceinline__ void mma16816(float* c, const uint32_t* a, const uint32_t* b) {
    asm volatile("mma.sync.aligned.m16n8k16.row.col.f32.bf16.bf16.f32 "
                 "{%0,%1,%2,%3}, {%4,%5,%6,%7}, {%8,%9}, {%0,%1,%2,%3};"
                 : "+f"(c[0]), "+f"(c[1]), "+f"(c[2]), "+f"(c[3])
                 : "r"(a[0]), "r"(a[1]), "r"(a[2]), "r"(a[3]), "r"(b[0]), "r"(b[1]));
}
__device__ __forceinline__ void cp16(uint32_t dst, const void* src) {
    asm volatile("cp.async.cg.shared.global [%0], [%1], 16;" :: "r"(dst), "l"(src) : "memory");
}
__device__ __forceinline__ void cp_commit() {
    asm volatile("cp.async.commit_group;" ::: "memory");
}
template <int N>
__device__ __forceinline__ void cp_wait() {
    asm volatile("cp.async.wait_group %0;" :: "n"(N) : "memory");
}

// ---------------------------------------------------------------------------
// Conversion kernels
// ---------------------------------------------------------------------------
__global__ __launch_bounds__(256) void split_x_kernel(const float* __restrict__ X)
{
    int i4 = blockIdx.x * 256 + threadIdx.x;
    float4 v = *(const float4*)(X + (size_t)i4 * 4);
    __nv_bfloat16 h0 = __float2bfloat16(v.x), h1 = __float2bfloat16(v.y);
    __nv_bfloat16 h2 = __float2bfloat16(v.z), h3 = __float2bfloat16(v.w);
    __nv_bfloat16 l0 = __float2bfloat16(v.x - __bfloat162float(h0));
    __nv_bfloat16 l1 = __float2bfloat16(v.y - __bfloat162float(h1));
    __nv_bfloat16 l2 = __float2bfloat16(v.z - __bfloat162float(h2));
    __nv_bfloat16 l3 = __float2bfloat16(v.w - __bfloat162float(h3));
    __nv_bfloat162 hA = {h0, h1}, hB = {h2, h3}, lA = {l0, l1}, lB = {l2, l3};
    *(__nv_bfloat162*)(g_Ahi + (size_t)i4 * 4)     = hA;
    *(__nv_bfloat162*)(g_Ahi + (size_t)i4 * 4 + 2) = hB;
    *(__nv_bfloat162*)(g_Alo + (size_t)i4 * 4)     = lA;
    *(__nv_bfloat162*)(g_Alo + (size_t)i4 * 4 + 2) = lB;
}

// gather head-major g_O -> row-major A [m][k], split
__global__ __launch_bounds__(256) void split_o_kernel()
{
    int i4 = blockIdx.x * 256 + threadIdx.x;
    int m = i4 >> 8, rem = i4 & 255;
    int k = rem * 4;
    int h = k >> 6, d = k & 63;
    int b_ = m >> 11, s_ = m & (SS - 1);
    float4 v = *(const float4*)(g_O + ((size_t)((b_*HH + h)*SS + s_)) * DD + d);
    __nv_bfloat16 h0 = __float2bfloat16(v.x), h1 = __float2bfloat16(v.y);
    __nv_bfloat16 h2 = __float2bfloat16(v.z), h3 = __float2bfloat16(v.w);
    __nv_bfloat16 l0 = __float2bfloat16(v.x - __bfloat162float(h0));
    __nv_bfloat16 l1 = __float2bfloat16(v.y - __bfloat162float(h1));
    __nv_bfloat16 l2 = __float2bfloat16(v.z - __bfloat162float(h2));
    __nv_bfloat16 l3 = __float2bfloat16(v.w - __bfloat162float(h3));
    size_t o = (size_t)m * EE + k;
    __nv_bfloat162 hA = {h0, h1}, hB = {h2, h3}, lA = {l0, l1}, lB = {l2, l3};
    *(__nv_bfloat162*)(g_Ahi + o)     = hA;
    *(__nv_bfloat162*)(g_Ahi + o + 2) = hB;
    *(__nv_bfloat162*)(g_Alo + o)     = lA;
    *(__nv_bfloat162*)(g_Alo + o + 2) = lB;
}

// transpose + split weights: W[k][n] fp32 -> g_W{hi,lo}[z][n][k] bf16
__global__ __launch_bounds__(256) void split_w_kernel(
    const float* __restrict__ wQ, const float* __restrict__ wK,
    const float* __restrict__ wV, const float* __restrict__ wO)
{
    __shared__ float ts[32][33];
    const float* src = (blockIdx.z == 0) ? wQ : (blockIdx.z == 1) ? wK :
                       (blockIdx.z == 2) ? wV : wO;
    size_t dst0 = (size_t)blockIdx.z * ND * EE;
    int t = threadIdx.x, tx = t & 31, ty = t >> 5;
    int k0 = blockIdx.x * 32, n0 = blockIdx.y * 32;
    #pragma unroll
    for (int i = 0; i < 4; ++i)
        ts[ty + i*8][tx] = src[(size_t)(k0 + ty + i*8) * ND + n0 + tx];
    __syncthreads();
    #pragma unroll
    for (int i = 0; i < 4; ++i) {
        float v = ts[tx][ty + i*8];
        __nv_bfloat16 hi = __float2bfloat16(v);
        __nv_bfloat16 lo = __float2bfloat16(v - __bfloat162float(hi));
        size_t o = dst0 + (size_t)(n0 + ty + i*8) * EE + k0 + tx;
        g_Whi[o] = hi;
        g_Wlo[o] = lo;
    }
}

// ---------------------------------------------------------------------------
// mma.sync bf16 split GEMM: C[M][N] = A x W^T + bias (W stored [n][k]).
// CTA 128x128, BK=32, 8 warps (warp tile 32x64), cp.async double buffer.
// smem rows padded to 40 bf16 (80B) for conflict-free ldmatrix.
// ---------------------------------------------------------------------------
#define GBK 32
#define ROWP 40                       // padded row elems
#define ARR_B (128*ROWP*2)            // 10240 bytes per array
#define BUF_B (4*ARR_B)               // 40960 bytes per buffer
#define GSMEM_TOTAL (2*BUF_B)         // 81920

__global__ __launch_bounds__(256) void mma_gemm_kernel(
    int woff, const float* __restrict__ b0, const float* __restrict__ b1,
    const float* __restrict__ b2, int headmajor, float* __restrict__ outr)
{
    extern __shared__ char smc[];
    const uint32_t SB = smem_u32(smc);
    const int t = threadIdx.x;
    const int wid = t >> 5, lane = t & 31;
    const int z = blockIdx.z;
    const int n0 = blockIdx.x * 128;
    const int m0 = blockIdx.y * 128;

    const __nv_bfloat16* Bh = g_Whi + (size_t)(woff + z) * ND * EE;
    const __nv_bfloat16* Bl = g_Wlo + (size_t)(woff + z) * ND * EE;
    const float* bias = (z == 0) ? b0 : (z == 1) ? b1 : b2;

    const int wm = (wid & 3) * 32;    // warp m offset in tile
    const int wn = (wid >> 2) * 64;   // warp n offset in tile

    // stage-load indexing: 512 uint4 per array, 2 per thread
    const int lrow0 = t >> 2, lcq = t & 3;   // +i*64 rows for i=0,1

    // ldmatrix lane address components
    const int j = lane >> 3, r = lane & 7;
    const int rowA = wm + ((j & 1) << 3) + r;
    const int colA = (j >> 1) << 3;
    const int rowB = wn + ((j >> 1) << 3) + r;
    const int colB = (j & 1) << 3;

    float acc[2][8][4];
    #pragma unroll
    for (int mt = 0; mt < 2; ++mt)
        #pragma unroll
        for (int nt = 0; nt < 8; ++nt)
            #pragma unroll
            for (int q = 0; q < 4; ++q) acc[mt][nt][q] = 0.0f;

    auto load_stage = [&](int kt, int buf) {
        const int k0 = kt * GBK;
        const uint32_t bb = SB + buf * BUF_B;
        #pragma unroll
        for (int i = 0; i < 2; ++i) {
            int row = lrow0 + i * 64;
            uint32_t so = row * (ROWP*2) + lcq * 16;
            size_t goA = (size_t)(m0 + row) * EE + k0 + lcq * 8;
            size_t goB = (size_t)(n0 + row) * EE + k0 + lcq * 8;
            cp16(bb + so,             g_Ahi + goA);
            cp16(bb + ARR_B + so,     g_Alo + goA);
            cp16(bb + 2*ARR_B + so,   Bh + goB);
            cp16(bb + 3*ARR_B + so,   Bl + goB);
        }
        cp_commit();
    };

    load_stage(0, 0);
    load_stage(1, 1);

    const int NSTAGE = EE / GBK;   // 32
    for (int kt = 0; kt < NSTAGE; ++kt) {
        if (kt >= NSTAGE - 2) cp_wait<0>(); else cp_wait<1>();
        __syncthreads();
        const uint32_t bb = SB + (kt & 1) * BUF_B;

        #pragma unroll
        for (int ks = 0; ks < 2; ++ks) {
            uint32_t ah[2][4], al_[2][4];
            #pragma unroll
            for (int mt = 0; mt < 2; ++mt) {
                uint32_t ad = bb + (uint32_t)(rowA + mt*16) * (ROWP*2)
                            + (uint32_t)(colA + ks*16) * 2;
                ldsm4(ah[mt], ad);
                ldsm4(al_[mt], ad + ARR_B);
            }
            #pragma unroll
            for (int ntp = 0; ntp < 4; ++ntp) {
                uint32_t bh[4], bl[4];
                uint32_t bd = bb + 2*ARR_B + (uint32_t)(rowB + ntp*16) * (ROWP*2)
                            + (uint32_t)(colB + ks*16) * 2;
                ldsm4(bh, bd);
                ldsm4(bl, bd + ARR_B);
                #pragma unroll
                for (int sub = 0; sub < 2; ++sub) {
                    uint32_t bbh[2] = {bh[sub*2], bh[sub*2+1]};
                    uint32_t bbl[2] = {bl[sub*2], bl[sub*2+1]};
                    const int nt = ntp*2 + sub;
                    #pragma unroll
                    for (int mt = 0; mt < 2; ++mt) {
                        mma16816(acc[mt][nt], ah[mt], bbh);
                        mma16816(acc[mt][nt], ah[mt], bbl);
                        mma16816(acc[mt][nt], al_[mt], bbh);
                    }
                }
            }
        }
        __syncthreads();
        if (kt + 2 < NSTAGE) load_stage(kt + 2, kt & 1);
    }

    // epilogue: thread holds c0,c1 at (m = base + lane/4, n = nt*8 + 2*(lane%4)),
    // c2,c3 at m+8
    const int ncl = (lane & 3) << 1;
    const int mrw = lane >> 2;
    if (headmajor) {
        const int h = (n0 + wn) >> 6;
        float* obase = (z == 0) ? g_Q : (z == 1) ? g_K : g_V;
        #pragma unroll
        for (int mt = 0; mt < 2; ++mt) {
            #pragma unroll
            for (int half = 0; half < 2; ++half) {
                int m = m0 + wm + mt*16 + mrw + half*8;
                int b_ = m >> 11, s_ = m & (SS - 1);
                float* op = obase + ((size_t)((b_*HH + h)*SS + s_)) * DD;
                #pragma unroll
                for (int nt = 0; nt < 8; ++nt) {
                    int nn = nt*8 + ncl;
                    float2 bv = *(const float2*)(bias + n0 + wn + nn);
                    float2 v;
                    v.x = acc[mt][nt][half*2+0] + bv.x;
                    v.y = acc[mt][nt][half*2+1] + bv.y;
                    *(float2*)(op + nn) = v;
                }
            }
        }
    } else {
        #pragma unroll
        for (int mt = 0; mt < 2; ++mt) {
            #pragma unroll
            for (int half = 0; half < 2; ++half) {
                int m = m0 + wm + mt*16 + mrw + half*8;
                float* op = outr + (size_t)m * ND + n0 + wn;
                #pragma unroll
                for (int nt = 0; nt < 8; ++nt) {
                    int nn = nt*8 + ncl;
                    float2 bv = *(const float2*)(bias + n0 + wn + nn);
                    float2 v;
                    v.x = acc[mt][nt][half*2+0] + bv.x;
                    v.y = acc[mt][nt][half*2+1] + bv.y;
                    *(float2*)(op + nn) = v;
                }
            }
        }
    }
}

// ---------------------------------------------------------------------------
// Flash attention (unchanged from R2): 128 q-rows, 64-col k-tiles, 256 thr.
// ---------------------------------------------------------------------------
#define ATTN_SMEM (80 * 1024)

__global__ __launch_bounds__(256) void attn_kernel(const int* __restrict__ mask)
{
    extern __shared__ float sm[];
    float* Qs  = sm;
    float* KPs = sm + 64*128;
    float* Vs  = sm + 2*64*128;

    const int t  = threadIdx.x;
    const int tx = t & 15, ty = t >> 4;
    const int bh = blockIdx.y;
    const int b_ = bh >> 4;
    const int qbase = blockIdx.x * 128;

    const float* Qg = g_Q + (size_t)bh * SS * DD + (size_t)qbase * DD;
    const float* Kg = g_K + (size_t)bh * SS * DD;
    const float* Vg = g_V + (size_t)bh * SS * DD;

    #pragma unroll
    for (int it = 0; it < 8; ++it) {
        int idx = t + it * 256;
        int r = idx & 127, dq = idx >> 7;
        float4 v = *(const float4*)(Qg + (size_t)r * DD + dq * 4);
        Qs[(dq*4+0)*128 + r] = v.x;
        Qs[(dq*4+1)*128 + r] = v.y;
        Qs[(dq*4+2)*128 + r] = v.z;
        Qs[(dq*4+3)*128 + r] = v.w;
    }

    float m_i[8], l_i[8], o[8][4];
    #pragma unroll
    for (int i = 0; i < 8; ++i) {
        m_i[i] = -INFINITY; l_i[i] = 0.0f;
        #pragma unroll
        for (int j = 0; j < 4; ++j) o[i][j] = 0.0f;
    }

    const int swz = (tx & 7) << 2;
    const int* mrow[2];
    mrow[0] = mask + ((size_t)b_ * SS + qbase + ty*4) * SS + tx*4;
    mrow[1] = mrow[0] + (size_t)64 * SS;

    for (int kt = 0; kt < SS / 64; ++kt) {
        const float* Kt = Kg + (size_t)kt * 64 * DD;
        const float* Vt = Vg + (size_t)kt * 64 * DD;
        __syncthreads();
        #pragma unroll
        for (int it = 0; it < 4; ++it) {
            int idx = t + it * 256;
            int r = idx & 63, dq = idx >> 6;
            float4 v = *(const float4*)(Kt + (size_t)r * DD + dq * 4);
            KPs[(dq*4+0)*64 + r] = v.x;
            KPs[(dq*4+1)*64 + r] = v.y;
            KPs[(dq*4+2)*64 + r] = v.z;
            KPs[(dq*4+3)*64 + r] = v.w;
        }
        #pragma unroll
        for (int it = 0; it < 4; ++it) {
            int idx = t + it * 256;
            int c = idx >> 4, q = idx & 15;
            *(float4*)&Vs[c*64 + q*4] = *(const float4*)(Vt + (size_t)c * DD + q*4);
        }
        __syncthreads();

        float sc[8][4];
        #pragma unroll
        for (int i = 0; i < 8; ++i)
            #pragma unroll
            for (int j = 0; j < 4; ++j) sc[i][j] = 0.0f;
        #pragma unroll 8
        for (int kk = 0; kk < 64; ++kk) {
            float4 a0 = *(const float4*)&Qs[kk*128 + ty*4];
            float4 a1 = *(const float4*)&Qs[kk*128 + ty*4 + 64];
            float4 b  = *(const float4*)&KPs[kk*64 + tx*4];
            float av[8] = {a0.x,a0.y,a0.z,a0.w, a1.x,a1.y,a1.z,a1.w};
            float bv[4] = {b.x,b.y,b.z,b.w};
            #pragma unroll
            for (int i = 0; i < 8; ++i)
                #pragma unroll
                for (int j = 0; j < 4; ++j)
                    sc[i][j] += av[i] * bv[j];
        }

        const int kb = kt * 64;
        #pragma unroll
        for (int i = 0; i < 8; ++i) {
            int4 mk = *(const int4*)(mrow[i >> 2] + (size_t)(i & 3) * SS + kb);
            sc[i][0] = mk.x ? sc[i][0] * 0.125f : -1e9f;
            sc[i][1] = mk.y ? sc[i][1] * 0.125f : -1e9f;
            sc[i][2] = mk.z ? sc[i][2] * 0.125f : -1e9f;
            sc[i][3] = mk.w ? sc[i][3] * 0.125f : -1e9f;
            float tm = fmaxf(fmaxf(sc[i][0], sc[i][1]), fmaxf(sc[i][2], sc[i][3]));
            tm = fmaxf(tm, __shfl_xor_sync(0xffffffffu, tm, 1));
            tm = fmaxf(tm, __shfl_xor_sync(0xffffffffu, tm, 2));
            tm = fmaxf(tm, __shfl_xor_sync(0xffffffffu, tm, 4));
            tm = fmaxf(tm, __shfl_xor_sync(0xffffffffu, tm, 8));
            float mn = fmaxf(m_i[i], tm);
            float al = __expf(m_i[i] - mn);
            m_i[i] = mn;
            float p0 = __expf(sc[i][0] - mn);
            float p1 = __expf(sc[i][1] - mn);
            float p2 = __expf(sc[i][2] - mn);
            float p3 = __expf(sc[i][3] - mn);
            sc[i][0] = p0; sc[i][1] = p1; sc[i][2] = p2; sc[i][3] = p3;
            float rs = (p0 + p1) + (p2 + p3);
            rs += __shfl_xor_sync(0xffffffffu, rs, 1);
            rs += __shfl_xor_sync(0xffffffffu, rs, 2);
            rs += __shfl_xor_sync(0xffffffffu, rs, 4);
            rs += __shfl_xor_sync(0xffffffffu, rs, 8);
            l_i[i] = l_i[i] * al + rs;
            o[i][0] *= al; o[i][1] *= al; o[i][2] *= al; o[i][3] *= al;
        }

        __syncthreads();
        {
            const int rb = (ty*4) ^ swz;
            #pragma unroll
            for (int j = 0; j < 4; ++j) {
                int c = tx*4 + j;
                float4 v0 = make_float4(sc[0][j], sc[1][j], sc[2][j], sc[3][j]);
                float4 v1 = make_float4(sc[4][j], sc[5][j], sc[6][j], sc[7][j]);
                *(float4*)&KPs[c*128 + rb]      = v0;
                *(float4*)&KPs[c*128 + rb + 64] = v1;
            }
        }
        __syncthreads();

        #pragma unroll 8
        for (int cc = 0; cc < 64; ++cc) {
            const int sw2 = ((cc >> 2) & 7) << 2;
            float4 a0 = *(const float4*)&KPs[cc*128 + ((ty*4) ^ sw2)];
            float4 a1 = *(const float4*)&KPs[cc*128 + ((ty*4) ^ sw2) + 64];
            float4 b  = *(const float4*)&Vs[cc*64 + tx*4];
            float av[8] = {a0.x,a0.y,a0.z,a0.w, a1.x,a1.y,a1.z,a1.w};
            float bv[4] = {b.x,b.y,b.z,b.w};
            #pragma unroll
            for (int i = 0; i < 8; ++i)
                #pragma unroll
                for (int j = 0; j < 4; ++j)
                    o[i][j] += av[i] * bv[j];
        }
    }

    #pragma unroll
    for (int i = 0; i < 8; ++i) {
        int row = qbase + ty*4 + (i & 3) + ((i >> 2) << 6);
        float inv = 1.0f / l_i[i];
        float4 v;
        v.x = o[i][0]*inv; v.y = o[i][1]*inv; v.z = o[i][2]*inv; v.w = o[i][3]*inv;
        *(float4*)(g_O + (size_t)bh * SS * DD + (size_t)row * DD + tx*4) = v;
    }
}

extern "C" void kernel_launch(void* const* d_in, const int* in_sizes, int n_in,
                              void* d_out, int out_size)
{
    const float* X    = (const float*)d_in[0];
    const int*   mask = (const int*)  d_in[1];
    const float* wQ   = (const float*)d_in[2];
    const float* bQ   = (const float*)d_in[3];
    const float* wK   = (const float*)d_in[4];
    const float* bK   = (const float*)d_in[5];
    const float* wV   = (const float*)d_in[6];
    const float* bV   = (const float*)d_in[7];
    const float* wO   = (const float*)d_in[8];
    const float* bO   = (const float*)d_in[9];
    float* out = (float*)d_out;

    cudaFuncSetAttribute(attn_kernel, cudaFuncAttributeMaxDynamicSharedMemorySize, ATTN_SMEM);
    cudaFuncSetAttribute(mma_gemm_kernel, cudaFuncAttributeMaxDynamicSharedMemorySize, GSMEM_TOTAL);

    split_x_kernel<<<MM*EE/1024, 256>>>(X);
    split_w_kernel<<<dim3(32, 32, 4), 256>>>(wQ, wK, wV, wO);
    mma_gemm_kernel<<<dim3(8, 64, 3), 256, GSMEM_TOTAL>>>(0, bQ, bK, bV, 1, nullptr);
    attn_kernel<<<dim3(16, 64), 256, ATTN_SMEM>>>(mask);
    split_o_kernel<<<MM*EE/1024, 256>>>();
    mma_gemm_kernel<<<dim3(8, 64, 1), 256, GSMEM_TOTAL>>>(3, bO, bO, bO, 0, out);
}

// round 5
// speedup vs baseline: 3.3009x; 1.8978x over previous
#include <cuda_runtime.h>
#include <cuda_bf16.h>
#include <math.h>
#include <stdint.h>

#define BB 4
#define SS 2048
#define EE 1024
#define HH 16
#define DD 64
#define ND 1024
#define MM (BB*SS)   // 8192

// bf16 split operands for GEMMs
__device__ __nv_bfloat16 g_Ahi[MM*EE];
__device__ __nv_bfloat16 g_Alo[MM*EE];
__device__ __nv_bfloat16 g_Whi[4*ND*EE];
__device__ __nv_bfloat16 g_Wlo[4*ND*EE];
// bf16 split Q/K head-major [bh][s][d]; V transposed [bh][d][s]
__device__ __nv_bfloat16 g_Qhi[BB*HH*SS*DD];
__device__ __nv_bfloat16 g_Qlo[BB*HH*SS*DD];
__device__ __nv_bfloat16 g_Khi[BB*HH*SS*DD];
__device__ __nv_bfloat16 g_Klo[BB*HH*SS*DD];
__device__ __nv_bfloat16 g_Vthi[BB*HH*DD*SS];
__device__ __nv_bfloat16 g_Vtlo[BB*HH*DD*SS];

// ---------------------------------------------------------------------------
// PTX helpers (compute_103-safe)
// ---------------------------------------------------------------------------
__device__ __forceinline__ uint32_t smem_u32(const void* p) {
    return (uint32_t)__cvta_generic_to_shared(p);
}
__device__ __forceinline__ void ldsm4(uint32_t* r, uint32_t addr) {
    asm volatile("ldmatrix.sync.aligned.m8n8.x4.shared.b16 {%0,%1,%2,%3}, [%4];"
                 : "=r"(r[0]), "=r"(r[1]), "=r"(r[2]), "=r"(r[3]) : "r"(addr));
}
__device__ __forceinline__ void mma16816(float* c, const uint32_t* a, const uint32_t* b) {
    asm volatile("mma.sync.aligned.m16n8k16.row.col.f32.bf16.bf16.f32 "
                 "{%0,%1,%2,%3}, {%4,%5,%6,%7}, {%8,%9}, {%0,%1,%2,%3};"
                 : "+f"(c[0]), "+f"(c[1]), "+f"(c[2]), "+f"(c[3])
                 : "r"(a[0]), "r"(a[1]), "r"(a[2]), "r"(a[3]), "r"(b[0]), "r"(b[1]));
}
__device__ __forceinline__ void cp16(uint32_t dst, const void* src) {
    asm volatile("cp.async.cg.shared.global [%0], [%1], 16;" :: "r"(dst), "l"(src) : "memory");
}
__device__ __forceinline__ void cp_commit() {
    asm volatile("cp.async.commit_group;" ::: "memory");
}
template <int N>
__device__ __forceinline__ void cp_wait() {
    asm volatile("cp.async.wait_group %0;" :: "n"(N) : "memory");
}
__device__ __forceinline__ uint32_t packbf(float a, float b) {
    __nv_bfloat162 t = __floats2bfloat162_rn(a, b);
    return *reinterpret_cast<uint32_t*>(&t);
}

// ---------------------------------------------------------------------------
// Conversion kernels
// ---------------------------------------------------------------------------
__global__ __launch_bounds__(256) void split_x_kernel(const float* __restrict__ X)
{
    int i4 = blockIdx.x * 256 + threadIdx.x;
    float4 v = *(const float4*)(X + (size_t)i4 * 4);
    __nv_bfloat16 h0 = __float2bfloat16(v.x), h1 = __float2bfloat16(v.y);
    __nv_bfloat16 h2 = __float2bfloat16(v.z), h3 = __float2bfloat16(v.w);
    __nv_bfloat16 l0 = __float2bfloat16(v.x - __bfloat162float(h0));
    __nv_bfloat16 l1 = __float2bfloat16(v.y - __bfloat162float(h1));
    __nv_bfloat16 l2 = __float2bfloat16(v.z - __bfloat162float(h2));
    __nv_bfloat16 l3 = __float2bfloat16(v.w - __bfloat162float(h3));
    __nv_bfloat162 hA = {h0, h1}, hB = {h2, h3}, lA = {l0, l1}, lB = {l2, l3};
    *(__nv_bfloat162*)(g_Ahi + (size_t)i4 * 4)     = hA;
    *(__nv_bfloat162*)(g_Ahi + (size_t)i4 * 4 + 2) = hB;
    *(__nv_bfloat162*)(g_Alo + (size_t)i4 * 4)     = lA;
    *(__nv_bfloat162*)(g_Alo + (size_t)i4 * 4 + 2) = lB;
}

// transpose + split weights: W[k][n] fp32 -> g_W{hi,lo}[z][n][k] bf16
__global__ __launch_bounds__(256) void split_w_kernel(
    const float* __restrict__ wQ, const float* __restrict__ wK,
    const float* __restrict__ wV, const float* __restrict__ wO)
{
    __shared__ float ts[32][33];
    const float* src = (blockIdx.z == 0) ? wQ : (blockIdx.z == 1) ? wK :
                       (blockIdx.z == 2) ? wV : wO;
    size_t dst0 = (size_t)blockIdx.z * ND * EE;
    int t = threadIdx.x, tx = t & 31, ty = t >> 5;
    int k0 = blockIdx.x * 32, n0 = blockIdx.y * 32;
    #pragma unroll
    for (int i = 0; i < 4; ++i)
        ts[ty + i*8][tx] = src[(size_t)(k0 + ty + i*8) * ND + n0 + tx];
    __syncthreads();
    #pragma unroll
    for (int i = 0; i < 4; ++i) {
        float v = ts[tx][ty + i*8];
        __nv_bfloat16 hi = __float2bfloat16(v);
        __nv_bfloat16 lo = __float2bfloat16(v - __bfloat162float(hi));
        size_t o = dst0 + (size_t)(n0 + ty + i*8) * EE + k0 + tx;
        g_Whi[o] = hi;
        g_Wlo[o] = lo;
    }
}

// ---------------------------------------------------------------------------
// mma.sync bf16 split GEMM (R4-verified core). headmajor=1: write bf16 splits
// of Q/K (head-major) and Vt (transposed); headmajor=0: fp32 row-major outr.
// ---------------------------------------------------------------------------
#define GBK 32
#define ROWP 40
#define ARR_B (128*ROWP*2)
#define BUF_B (4*ARR_B)
#define GSMEM_TOTAL (2*BUF_B)

__global__ __launch_bounds__(256) void mma_gemm_kernel(
    int woff, const float* __restrict__ b0, const float* __restrict__ b1,
    const float* __restrict__ b2, int headmajor, float* __restrict__ outr)
{
    extern __shared__ char smc[];
    const uint32_t SB = smem_u32(smc);
    const int t = threadIdx.x;
    const int wid = t >> 5, lane = t & 31;
    const int z = blockIdx.z;
    const int n0 = blockIdx.x * 128;
    const int m0 = blockIdx.y * 128;

    const __nv_bfloat16* Bh = g_Whi + (size_t)(woff + z) * ND * EE;
    const __nv_bfloat16* Bl = g_Wlo + (size_t)(woff + z) * ND * EE;
    const float* bias = (z == 0) ? b0 : (z == 1) ? b1 : b2;

    const int wm = (wid & 3) * 32;
    const int wn = (wid >> 2) * 64;
    const int lrow0 = t >> 2, lcq = t & 3;

    const int j = lane >> 3, r = lane & 7;
    const int rowA = wm + ((j & 1) << 3) + r;
    const int colA = (j >> 1) << 3;
    const int rowB = wn + ((j >> 1) << 3) + r;
    const int colB = (j & 1) << 3;

    float acc[2][8][4];
    #pragma unroll
    for (int mt = 0; mt < 2; ++mt)
        #pragma unroll
        for (int nt = 0; nt < 8; ++nt)
            #pragma unroll
            for (int q = 0; q < 4; ++q) acc[mt][nt][q] = 0.0f;

    auto load_stage = [&](int kt, int buf) {
        const int k0 = kt * GBK;
        const uint32_t bb = SB + buf * BUF_B;
        #pragma unroll
        for (int i = 0; i < 2; ++i) {
            int row = lrow0 + i * 64;
            uint32_t so = row * (ROWP*2) + lcq * 16;
            size_t goA = (size_t)(m0 + row) * EE + k0 + lcq * 8;
            size_t goB = (size_t)(n0 + row) * EE + k0 + lcq * 8;
            cp16(bb + so,             g_Ahi + goA);
            cp16(bb + ARR_B + so,     g_Alo + goA);
            cp16(bb + 2*ARR_B + so,   Bh + goB);
            cp16(bb + 3*ARR_B + so,   Bl + goB);
        }
        cp_commit();
    };

    load_stage(0, 0);
    load_stage(1, 1);

    const int NSTAGE = EE / GBK;
    for (int kt = 0; kt < NSTAGE; ++kt) {
        if (kt >= NSTAGE - 2) cp_wait<0>(); else cp_wait<1>();
        __syncthreads();
        const uint32_t bb = SB + (kt & 1) * BUF_B;

        #pragma unroll
        for (int ks = 0; ks < 2; ++ks) {
            uint32_t ah[2][4], al_[2][4];
            #pragma unroll
            for (int mt = 0; mt < 2; ++mt) {
                uint32_t ad = bb + (uint32_t)(rowA + mt*16) * (ROWP*2)
                            + (uint32_t)(colA + ks*16) * 2;
                ldsm4(ah[mt], ad);
                ldsm4(al_[mt], ad + ARR_B);
            }
            #pragma unroll
            for (int ntp = 0; ntp < 4; ++ntp) {
                uint32_t bh[4], bl[4];
                uint32_t bd = bb + 2*ARR_B + (uint32_t)(rowB + ntp*16) * (ROWP*2)
                            + (uint32_t)(colB + ks*16) * 2;
                ldsm4(bh, bd);
                ldsm4(bl, bd + ARR_B);
                #pragma unroll
                for (int sub = 0; sub < 2; ++sub) {
                    uint32_t bbh[2] = {bh[sub*2], bh[sub*2+1]};
                    uint32_t bbl[2] = {bl[sub*2], bl[sub*2+1]};
                    const int nt = ntp*2 + sub;
                    #pragma unroll
                    for (int mt = 0; mt < 2; ++mt) {
                        mma16816(acc[mt][nt], ah[mt], bbh);
                        mma16816(acc[mt][nt], ah[mt], bbl);
                        mma16816(acc[mt][nt], al_[mt], bbh);
                    }
                }
            }
        }
        __syncthreads();
        if (kt + 2 < NSTAGE) load_stage(kt + 2, kt & 1);
    }

    const int ncl = (lane & 3) << 1;
    const int mrw = lane >> 2;
    if (headmajor) {
        const int h = (n0 + wn) >> 6;
        if (z < 2) {
            __nv_bfloat16* dh = z ? g_Khi : g_Qhi;
            __nv_bfloat16* dl = z ? g_Klo : g_Qlo;
            #pragma unroll
            for (int mt = 0; mt < 2; ++mt) {
                #pragma unroll
                for (int half = 0; half < 2; ++half) {
                    int m = m0 + wm + mt*16 + mrw + half*8;
                    int b_ = m >> 11, s_ = m & (SS - 1);
                    size_t rb = ((size_t)(b_*HH + h) * SS + s_) * DD;
                    #pragma unroll
                    for (int nt = 0; nt < 8; ++nt) {
                        int nn = nt*8 + ncl;
                        float2 bv = *(const float2*)(bias + n0 + wn + nn);
                        float vx = acc[mt][nt][half*2+0] + bv.x;
                        float vy = acc[mt][nt][half*2+1] + bv.y;
                        __nv_bfloat16 hx = __float2bfloat16(vx);
                        __nv_bfloat16 hy = __float2bfloat16(vy);
                        __nv_bfloat16 lx = __float2bfloat16(vx - __bfloat162float(hx));
                        __nv_bfloat16 ly = __float2bfloat16(vy - __bfloat162float(hy));
                        __nv_bfloat162 ph = {hx, hy}, pl = {lx, ly};
                        *(__nv_bfloat162*)(dh + rb + nn) = ph;
                        *(__nv_bfloat162*)(dl + rb + nn) = pl;
                    }
                }
            }
        } else {
            #pragma unroll
            for (int mt = 0; mt < 2; ++mt) {
                #pragma unroll
                for (int half = 0; half < 2; ++half) {
                    int m = m0 + wm + mt*16 + mrw + half*8;
                    int b_ = m >> 11, s_ = m & (SS - 1);
                    size_t base = (size_t)(b_*HH + h) * DD * SS;
                    #pragma unroll
                    for (int nt = 0; nt < 8; ++nt) {
                        int nn = nt*8 + ncl;
                        float2 bv = *(const float2*)(bias + n0 + wn + nn);
                        float vx = acc[mt][nt][half*2+0] + bv.x;
                        float vy = acc[mt][nt][half*2+1] + bv.y;
                        __nv_bfloat16 hx = __float2bfloat16(vx);
                        __nv_bfloat16 hy = __float2bfloat16(vy);
                        g_Vthi[base + (size_t)nn     * SS + s_] = hx;
                        g_Vthi[base + (size_t)(nn+1) * SS + s_] = hy;
                        g_Vtlo[base + (size_t)nn     * SS + s_] =
                            __float2bfloat16(vx - __bfloat162float(hx));
                        g_Vtlo[base + (size_t)(nn+1) * SS + s_] =
                            __float2bfloat16(vy - __bfloat162float(hy));
                    }
                }
            }
        }
    } else {
        #pragma unroll
        for (int mt = 0; mt < 2; ++mt) {
            #pragma unroll
            for (int half = 0; half < 2; ++half) {
                int m = m0 + wm + mt*16 + mrw + half*8;
                float* op = outr + (size_t)m * ND + n0 + wn;
                #pragma unroll
                for (int nt = 0; nt < 8; ++nt) {
                    int nn = nt*8 + ncl;
                    float2 bv = *(const float2*)(bias + n0 + wn + nn);
                    float2 v;
                    v.x = acc[mt][nt][half*2+0] + bv.x;
                    v.y = acc[mt][nt][half*2+1] + bv.y;
                    *(float2*)(op + nn) = v;
                }
            }
        }
    }
}

// ---------------------------------------------------------------------------
// MMA flash attention: per (bh, 128-q tile); 128 threads (4 warps, warp m=32);
// k-tiles of 64. bf16 split QK^T (3 mma) + online softmax + split PV (3 mma).
// P stays in registers (S-accum layout == A-fragment layout).
// smem: Q hi/lo (128x64 pad 72) + 2 buf x {K hi/lo, Vt hi/lo} (64x64 pad 72).
// ---------------------------------------------------------------------------
#define AROWB 144                       // 72 elems * 2B
#define AQ_B (128*AROWB)                // 18432
#define AK_B (64*AROWB)                 // 9216
#define AOFF_KV 36864
#define AKV_STRIDE 36864
#define ATTN_SMEM 110592

__global__ __launch_bounds__(128) void attn_mma_kernel(const int* __restrict__ mask)
{
    extern __shared__ char smc[];
    const uint32_t SB = smem_u32(smc);
    const int t = threadIdx.x, wid = t >> 5, lane = t & 31;
    const int bh = blockIdx.y, b_ = bh >> 4, h = bh & 15;
    const int q0 = blockIdx.x * 128;
    const int wm = wid * 32;

    const __nv_bfloat16* Qh = g_Qhi + (size_t)bh*SS*DD + (size_t)q0*DD;
    const __nv_bfloat16* Ql = g_Qlo + (size_t)bh*SS*DD + (size_t)q0*DD;
    const __nv_bfloat16* Kh = g_Khi + (size_t)bh*SS*DD;
    const __nv_bfloat16* Kl = g_Klo + (size_t)bh*SS*DD;
    const __nv_bfloat16* Vh = g_Vthi + (size_t)bh*DD*SS;
    const __nv_bfloat16* Vl = g_Vtlo + (size_t)bh*DD*SS;

    // Q load (group with kv0)
    #pragma unroll
    for (int i = 0; i < 8; ++i) {
        int idx = t + i * 128;
        int row = idx >> 3, q = idx & 7;
        cp16(SB + row*AROWB + q*16,        Qh + (size_t)row*DD + q*8);
        cp16(SB + AQ_B + row*AROWB + q*16, Ql + (size_t)row*DD + q*8);
    }
    auto load_kv = [&](int kt, int buf) {
        const int k0 = kt * 64;
        const uint32_t bb = SB + AOFF_KV + buf * AKV_STRIDE;
        #pragma unroll
        for (int i = 0; i < 4; ++i) {
            int idx = t + i * 128;
            int row = idx >> 3, q = idx & 7;
            cp16(bb + row*AROWB + q*16,          Kh + (size_t)(k0+row)*DD + q*8);
            cp16(bb + AK_B + row*AROWB + q*16,   Kl + (size_t)(k0+row)*DD + q*8);
            cp16(bb + 2*AK_B + row*AROWB + q*16, Vh + (size_t)row*SS + k0 + q*8);
            cp16(bb + 3*AK_B + row*AROWB + q*16, Vl + (size_t)row*SS + k0 + q*8);
        }
        cp_commit();
    };
    load_kv(0, 0);   // group0 = Q + kv0
    load_kv(1, 1);   // group1

    const int j = lane >> 3, r_ = lane & 7;
    const int rowA = wm + ((j & 1) << 3) + r_;
    const int colA = (j >> 1) << 3;
    const int rowB = ((j >> 1) << 3) + r_;
    const int colB = (j & 1) << 3;
    const int ncl2 = (lane & 3) << 1;
    const int mrw = lane >> 2;

    const int* mp[2][2];
    #pragma unroll
    for (int mt = 0; mt < 2; ++mt)
        #pragma unroll
        for (int hf = 0; hf < 2; ++hf)
            mp[mt][hf] = mask + ((size_t)b_*SS + (q0 + wm + mt*16 + hf*8 + mrw)) * SS;

    float o[2][8][4];
    float m_i[2][2], l_i[2][2];
    #pragma unroll
    for (int mt = 0; mt < 2; ++mt) {
        m_i[mt][0] = -INFINITY; m_i[mt][1] = -INFINITY;
        l_i[mt][0] = 0.0f; l_i[mt][1] = 0.0f;
        #pragma unroll
        for (int dn = 0; dn < 8; ++dn)
            #pragma unroll
            for (int q = 0; q < 4; ++q) o[mt][dn][q] = 0.0f;
    }

    for (int kt = 0; kt < SS/64; ++kt) {
        if (kt >= SS/64 - 2) cp_wait<0>(); else cp_wait<1>();
        __syncthreads();
        const uint32_t bb = SB + AOFF_KV + (kt & 1) * AKV_STRIDE;

        // S = Q K^T (split, 3 passes)
        float s[2][8][4];
        #pragma unroll
        for (int mt = 0; mt < 2; ++mt)
            #pragma unroll
            for (int jn = 0; jn < 8; ++jn)
                #pragma unroll
                for (int q = 0; q < 4; ++q) s[mt][jn][q] = 0.0f;

        #pragma unroll
        for (int ks = 0; ks < 4; ++ks) {
            uint32_t ah[2][4], al_[2][4];
            #pragma unroll
            for (int mt = 0; mt < 2; ++mt) {
                uint32_t aq = SB + (uint32_t)(rowA + mt*16)*AROWB + (uint32_t)(colA + ks*16)*2;
                ldsm4(ah[mt], aq);
                ldsm4(al_[mt], aq + AQ_B);
            }
            #pragma unroll
            for (int jnp = 0; jnp < 4; ++jnp) {
                uint32_t kh4[4], kl4[4];
                uint32_t ka = bb + (uint32_t)(rowB + jnp*16)*AROWB + (uint32_t)(colB + ks*16)*2;
                ldsm4(kh4, ka);
                ldsm4(kl4, ka + AK_B);
                #pragma unroll
                for (int sub = 0; sub < 2; ++sub) {
                    uint32_t bh2[2] = {kh4[sub*2], kh4[sub*2+1]};
                    uint32_t bl2[2] = {kl4[sub*2], kl4[sub*2+1]};
                    const int jn = jnp*2 + sub;
                    #pragma unroll
                    for (int mt = 0; mt < 2; ++mt) {
                        mma16816(s[mt][jn], ah[mt], bh2);
                        mma16816(s[mt][jn], ah[mt], bl2);
                        mma16816(s[mt][jn], al_[mt], bh2);
                    }
                }
            }
        }

        // mask + scale
        const int kb = kt * 64;
        #pragma unroll
        for (int mt = 0; mt < 2; ++mt) {
            #pragma unroll
            for (int jn = 0; jn < 8; ++jn) {
                const int coff = kb + jn*8 + ncl2;
                int2 mk0 = *(const int2*)(mp[mt][0] + coff);
                int2 mk1 = *(const int2*)(mp[mt][1] + coff);
                s[mt][jn][0] = mk0.x ? s[mt][jn][0]*0.125f : -1e9f;
                s[mt][jn][1] = mk0.y ? s[mt][jn][1]*0.125f : -1e9f;
                s[mt][jn][2] = mk1.x ? s[mt][jn][2]*0.125f : -1e9f;
                s[mt][jn][3] = mk1.y ? s[mt][jn][3]*0.125f : -1e9f;
            }
        }

        // online softmax per (mt, half-row)
        float alsc[2][2];
        #pragma unroll
        for (int mt = 0; mt < 2; ++mt) {
            #pragma unroll
            for (int hf = 0; hf < 2; ++hf) {
                float mx = -INFINITY;
                #pragma unroll
                for (int jn = 0; jn < 8; ++jn)
                    mx = fmaxf(mx, fmaxf(s[mt][jn][hf*2], s[mt][jn][hf*2+1]));
                mx = fmaxf(mx, __shfl_xor_sync(0xffffffffu, mx, 1));
                mx = fmaxf(mx, __shfl_xor_sync(0xffffffffu, mx, 2));
                float mn = fmaxf(m_i[mt][hf], mx);
                float al = __expf(m_i[mt][hf] - mn);
                m_i[mt][hf] = mn;
                float rs = 0.0f;
                #pragma unroll
                for (int jn = 0; jn < 8; ++jn) {
                    float p0 = __expf(s[mt][jn][hf*2]   - mn);
                    float p1 = __expf(s[mt][jn][hf*2+1] - mn);
                    s[mt][jn][hf*2]   = p0;
                    s[mt][jn][hf*2+1] = p1;
                    rs += p0 + p1;
                }
                rs += __shfl_xor_sync(0xffffffffu, rs, 1);
                rs += __shfl_xor_sync(0xffffffffu, rs, 2);
                l_i[mt][hf] = l_i[mt][hf] * al + rs;
                alsc[mt][hf] = al;
            }
        }
        #pragma unroll
        for (int mt = 0; mt < 2; ++mt)
            #pragma unroll
            for (int dn = 0; dn < 8; ++dn) {
                o[mt][dn][0] *= alsc[mt][0];
                o[mt][dn][1] *= alsc[mt][0];
                o[mt][dn][2] *= alsc[mt][1];
                o[mt][dn][3] *= alsc[mt][1];
            }

        // O += P V (split, 3 passes); P packed from s regs per k16-step
        #pragma unroll
        for (int ks = 0; ks < 4; ++ks) {
            uint32_t pah[2][4], pal[2][4];
            #pragma unroll
            for (int mt = 0; mt < 2; ++mt) {
                const int j0 = 2*ks, j1 = 2*ks + 1;
                float p00 = s[mt][j0][0], p01 = s[mt][j0][1];
                float p02 = s[mt][j0][2], p03 = s[mt][j0][3];
                float p10 = s[mt][j1][0], p11 = s[mt][j1][1];
                float p12 = s[mt][j1][2], p13 = s[mt][j1][3];
                pah[mt][0] = packbf(p00, p01);
                pah[mt][1] = packbf(p02, p03);
                pah[mt][2] = packbf(p10, p11);
                pah[mt][3] = packbf(p12, p13);
                float h00 = __bfloat162float(__float2bfloat16(p00));
                float h01 = __bfloat162float(__float2bfloat16(p01));
                float h02 = __bfloat162float(__float2bfloat16(p02));
                float h03 = __bfloat162float(__float2bfloat16(p03));
                float h10 = __bfloat162float(__float2bfloat16(p10));
                float h11 = __bfloat162float(__float2bfloat16(p11));
                float h12 = __bfloat162float(__float2bfloat16(p12));
                float h13 = __bfloat162float(__float2bfloat16(p13));
                pal[mt][0] = packbf(p00 - h00, p01 - h01);
                pal[mt][1] = packbf(p02 - h02, p03 - h03);
                pal[mt][2] = packbf(p10 - h10, p11 - h11);
                pal[mt][3] = packbf(p12 - h12, p13 - h13);
            }
            #pragma unroll
            for (int dnp = 0; dnp < 4; ++dnp) {
                uint32_t vh4[4], vl4[4];
                uint32_t va = bb + 2*AK_B + (uint32_t)(rowB + dnp*16)*AROWB
                            + (uint32_t)(colB + ks*16)*2;
                ldsm4(vh4, va);
                ldsm4(vl4, va + AK_B);
                #pragma unroll
                for (int sub = 0; sub < 2; ++sub) {
                    uint32_t vbh[2] = {vh4[sub*2], vh4[sub*2+1]};
                    uint32_t vbl[2] = {vl4[sub*2], vl4[sub*2+1]};
                    const int dn = dnp*2 + sub;
                    #pragma unroll
                    for (int mt = 0; mt < 2; ++mt) {
                        mma16816(o[mt][dn], pah[mt], vbh);
                        mma16816(o[mt][dn], pah[mt], vbl);
                        mma16816(o[mt][dn], pal[mt], vbh);
                    }
                }
            }
        }

        __syncthreads();
        if (kt + 2 < SS/64) load_kv(kt + 2, kt & 1);
    }

    // normalize + write bf16 splits to out-proj A buffers [m][h*64+d]
    #pragma unroll
    for (int mt = 0; mt < 2; ++mt) {
        #pragma unroll
        for (int hf = 0; hf < 2; ++hf) {
            const int q = q0 + wm + mt*16 + hf*8 + mrw;
            const float inv = 1.0f / l_i[mt][hf];
            size_t base = ((size_t)b_*SS + q) * ND + h*64;
            #pragma unroll
            for (int dn = 0; dn < 8; ++dn) {
                int d0 = dn*8 + ncl2;
                float v0 = o[mt][dn][hf*2]   * inv;
                float v1 = o[mt][dn][hf*2+1] * inv;
                __nv_bfloat16 h0 = __float2bfloat16(v0);
                __nv_bfloat16 h1 = __float2bfloat16(v1);
                __nv_bfloat16 l0 = __float2bfloat16(v0 - __bfloat162float(h0));
                __nv_bfloat16 l1 = __float2bfloat16(v1 - __bfloat162float(h1));
                __nv_bfloat162 ph = {h0, h1}, pl = {l0, l1};
                *(__nv_bfloat162*)(g_Ahi + base + d0) = ph;
                *(__nv_bfloat162*)(g_Alo + base + d0) = pl;
            }
        }
    }
}

extern "C" void kernel_launch(void* const* d_in, const int* in_sizes, int n_in,
                              void* d_out, int out_size)
{
    const float* X    = (const float*)d_in[0];
    const int*   mask = (const int*)  d_in[1];
    const float* wQ   = (const float*)d_in[2];
    const float* bQ   = (const float*)d_in[3];
    const float* wK   = (const float*)d_in[4];
    const float* bK   = (const float*)d_in[5];
    const float* wV   = (const float*)d_in[6];
    const float* bV   = (const float*)d_in[7];
    const float* wO   = (const float*)d_in[8];
    const float* bO   = (const float*)d_in[9];
    float* out = (float*)d_out;

    cudaFuncSetAttribute(mma_gemm_kernel, cudaFuncAttributeMaxDynamicSharedMemorySize, GSMEM_TOTAL);
    cudaFuncSetAttribute(attn_mma_kernel, cudaFuncAttributeMaxDynamicSharedMemorySize, ATTN_SMEM);

    split_x_kernel<<<MM*EE/1024, 256>>>(X);
    split_w_kernel<<<dim3(32, 32, 4), 256>>>(wQ, wK, wV, wO);
    mma_gemm_kernel<<<dim3(8, 64, 3), 256, GSMEM_TOTAL>>>(0, bQ, bK, bV, 1, nullptr);
    attn_mma_kernel<<<dim3(16, 64), 128, ATTN_SMEM>>>(mask);
    mma_gemm_kernel<<<dim3(8, 64, 1), 256, GSMEM_TOTAL>>>(3, bO, bO, bO, 0, out);
}